// round 3
// baseline (speedup 1.0000x reference)
#include <cuda_runtime.h>
#include <cuda_bf16.h>
#include <math.h>
#include <stdint.h>

#define Bb 2
#define Nn 2048
#define Cc 1024
#define Hh 16
#define Dd 64
#define Mtot (Bb*Nn)     /* 4096 */
#define K3  (3*Cc)       /* 3072 */
#define SCALE 0.125f     /* 1/sqrt(64) */

// ---------------- scratch (static device arrays; no runtime alloc) ----------
__device__ float g_q[(size_t)Bb*Hh*Nn*Dd];   // [B,H,N,D]
__device__ float g_k[(size_t)Bb*Hh*Nn*Dd];
__device__ float g_v[(size_t)Bb*Hh*Nn*Dd];
__device__ float g_o[(size_t)Mtot*Cc];       // attention out, [B,N,H,D]
__device__ float g_cos[Nn*(Dd/2)];
__device__ float g_sin[Nn*(Dd/2)];

// ---------------- RoPE tables ----------------
__global__ void rope_init_kernel() {
    int idx = blockIdx.x * blockDim.x + threadIdx.x;
    if (idx >= Nn * (Dd/2)) return;
    int n = idx / (Dd/2);
    int i = idx % (Dd/2);
    float invf = powf(10000.0f, -(float)i / (float)(Dd/2));
    float f = (float)n * invf;
    g_cos[idx] = cosf(f);
    g_sin[idx] = sinf(f);
}

// ======================= bf16x3 warp-MMA GEMM ==============================
// mma.sync m16n8k16 bf16 -> f32.  Split each fp32 operand into bf16 hi+lo,
// accumulate ah*bh + al*bh + ah*bl (al*bl dropped, ~2^-16 relative).

__device__ __forceinline__ void mma_bf16(float* c, const uint32_t* a, const uint32_t* b) {
    asm volatile("mma.sync.aligned.m16n8k16.row.col.f32.bf16.bf16.f32 "
        "{%0,%1,%2,%3}, {%4,%5,%6,%7}, {%8,%9}, {%0,%1,%2,%3};"
        : "+f"(c[0]), "+f"(c[1]), "+f"(c[2]), "+f"(c[3])
        : "r"(a[0]), "r"(a[1]), "r"(a[2]), "r"(a[3]), "r"(b[0]), "r"(b[1]));
}

__device__ __forceinline__ void split_bf(float x, uint16_t& h, uint16_t& lo) {
    __nv_bfloat16 hb = __float2bfloat16_rn(x);
    float r = x - __bfloat162float(hb);
    __nv_bfloat16 lb = __float2bfloat16_rn(r);
    h  = *(uint16_t*)&hb;
    lo = *(uint16_t*)&lb;
}

#define APAD 40   /* bf16 row stride for A & B tiles (conflict-free) */

// Shared mainloop: A row-major [*,lda], B row-major [K,ldb]; B is transposed
// into smem as [n][k]. Leaves 128x128 fp32 result in acc (warp layout).
// Block = 256 threads, warps 2(M)x4(N), warp tile 64x32.
__device__ __forceinline__ void gemm_mainloop_bf16x3(
    const float* __restrict__ A, int lda,
    const float* __restrict__ Bw, int ldb,
    int bm, int bn, int KTOT,
    uint16_t* sAh, uint16_t* sAl, uint16_t* sBh, uint16_t* sBl,
    float acc[4][4][4])
{
    int tid = threadIdx.x;
    int l = tid & 31;
    int w = tid >> 5;
    int wm = (w >> 2) * 64;
    int wn = (w & 3) * 32;

#pragma unroll
    for (int mf = 0; mf < 4; mf++)
#pragma unroll
        for (int nf = 0; nf < 4; nf++)
#pragma unroll
            for (int i = 0; i < 4; i++) acc[mf][nf][i] = 0.0f;

    const int KT = KTOT / 32;
    for (int kt = 0; kt < KT; kt++) {
        // ---- gmem -> regs ----
        float4 av[4], bv[4];
#pragma unroll
        for (int i = 0; i < 4; i++) {
            int idx = tid + 256 * i;
            int ar = idx >> 3, ag = idx & 7;
            av[i] = *(const float4*)(A + (size_t)(bm + ar) * lda + kt * 32 + ag * 4);
            int bk = idx >> 5, b4 = idx & 31;
            bv[i] = *(const float4*)(Bw + (size_t)(kt * 32 + bk) * ldb + bn + b4 * 4);
        }
        __syncthreads();   // previous iter's fragment reads done

        // ---- store A (hi/lo), rows x k, packed pairs ----
#pragma unroll
        for (int i = 0; i < 4; i++) {
            int idx = tid + 256 * i;
            int ar = idx >> 3, ag = idx & 7;
            uint16_t h0,l0,h1,l1,h2,l2,h3,l3;
            split_bf(av[i].x, h0, l0); split_bf(av[i].y, h1, l1);
            split_bf(av[i].z, h2, l2); split_bf(av[i].w, h3, l3);
            uint32_t* ph = (uint32_t*)&sAh[ar * APAD + ag * 4];
            uint32_t* pl = (uint32_t*)&sAl[ar * APAD + ag * 4];
            ph[0] = (uint32_t)h0 | ((uint32_t)h1 << 16);
            ph[1] = (uint32_t)h2 | ((uint32_t)h3 << 16);
            pl[0] = (uint32_t)l0 | ((uint32_t)l1 << 16);
            pl[1] = (uint32_t)l2 | ((uint32_t)l3 << 16);
        }
        // ---- store B transposed (hi/lo): sB[n][k] ----
#pragma unroll
        for (int i = 0; i < 4; i++) {
            int idx = tid + 256 * i;
            int bk = idx >> 5, b4 = idx & 31;
            float vs[4] = {bv[i].x, bv[i].y, bv[i].z, bv[i].w};
#pragma unroll
            for (int j = 0; j < 4; j++) {
                uint16_t h, lo;
                split_bf(vs[j], h, lo);
                int n = b4 * 4 + j;
                sBh[n * APAD + bk] = h;
                sBl[n * APAD + bk] = lo;
            }
        }
        __syncthreads();

        // ---- MMA: 2 k-steps of 16 ----
#pragma unroll
        for (int ks = 0; ks < 2; ks++) {
            int kc = ks * 16 + (l & 3) * 2;
            int r0 = wm + (l >> 2);
            uint32_t ah[4][4], al[4][4], bh[4][2], bl[4][2];
#pragma unroll
            for (int mf = 0; mf < 4; mf++) {
                int r = r0 + mf * 16;
                ah[mf][0] = *(uint32_t*)&sAh[(r    ) * APAD + kc];
                ah[mf][1] = *(uint32_t*)&sAh[(r + 8) * APAD + kc];
                ah[mf][2] = *(uint32_t*)&sAh[(r    ) * APAD + kc + 8];
                ah[mf][3] = *(uint32_t*)&sAh[(r + 8) * APAD + kc + 8];
                al[mf][0] = *(uint32_t*)&sAl[(r    ) * APAD + kc];
                al[mf][1] = *(uint32_t*)&sAl[(r + 8) * APAD + kc];
                al[mf][2] = *(uint32_t*)&sAl[(r    ) * APAD + kc + 8];
                al[mf][3] = *(uint32_t*)&sAl[(r + 8) * APAD + kc + 8];
            }
#pragma unroll
            for (int nf = 0; nf < 4; nf++) {
                int n = wn + nf * 8 + (l >> 2);
                bh[nf][0] = *(uint32_t*)&sBh[n * APAD + kc];
                bh[nf][1] = *(uint32_t*)&sBh[n * APAD + kc + 8];
                bl[nf][0] = *(uint32_t*)&sBl[n * APAD + kc];
                bl[nf][1] = *(uint32_t*)&sBl[n * APAD + kc + 8];
            }
#pragma unroll
            for (int mf = 0; mf < 4; mf++)
#pragma unroll
                for (int nf = 0; nf < 4; nf++) {
                    mma_bf16(acc[mf][nf], ah[mf], bh[nf]);
                    mma_bf16(acc[mf][nf], al[mf], bh[nf]);
                    mma_bf16(acc[mf][nf], ah[mf], bl[nf]);
                }
        }
    }
}

// ---------------- GEMM1: qkv = x @ Wqkv, fused RoPE epilogue ----------------
__global__ __launch_bounds__(256) void qkv_mma_gemm(
    const float* __restrict__ A, const float* __restrict__ Bw)
{
    __shared__ uint16_t sAh[128 * APAD], sAl[128 * APAD];
    __shared__ uint16_t sBh[128 * APAD], sBl[128 * APAD];

    int bm = blockIdx.y * 128, bn = blockIdx.x * 128;
    float acc[4][4][4];
    gemm_mainloop_bf16x3(A, Cc, Bw, K3, bm, bn, Cc, sAh, sAl, sBh, sBl, acc);

    int tid = threadIdx.x;
    int l = tid & 31;
    int w = tid >> 5;
    int wm = (w >> 2) * 64, wn = (w & 3) * 32;

#pragma unroll
    for (int mf = 0; mf < 4; mf++) {
#pragma unroll
        for (int half = 0; half < 2; half++) {
            int row = bm + wm + mf * 16 + (l >> 2) + half * 8;
            int b = row >> 11;
            int tok = row & (Nn - 1);
#pragma unroll
            for (int nf = 0; nf < 4; nf++) {
                int col = bn + wn + nf * 8 + (l & 3) * 2;   // even
                float y0 = acc[mf][nf][half * 2 + 0];
                float y1 = acc[mf][nf][half * 2 + 1];
                int region = col >> 10;
                int cc = col & 1023;
                int h = cc >> 6;
                int dd = cc & 63;
                size_t base = ((size_t)(b * Hh + h) * Nn + tok) * Dd;
                if (region == 2) {
                    *(float2*)(g_v + base + dd) = make_float2(y0, y1);
                } else {
                    float* dst = region ? g_k : g_q;
                    int i1 = dd >> 1;
                    float cs = g_cos[tok * 32 + i1];
                    float sn = g_sin[tok * 32 + i1];
                    dst[base + i1]      = y0 * cs - y1 * sn;
                    dst[base + i1 + 32] = y0 * sn + y1 * cs;
                }
            }
        }
    }
}

// ---------------- GEMM3: out = g_o @ Wout + bout ---------------------------
__global__ __launch_bounds__(256) void out_mma_gemm(
    const float* __restrict__ Bw, const float* __restrict__ bias,
    float* __restrict__ out)
{
    __shared__ uint16_t sAh[128 * APAD], sAl[128 * APAD];
    __shared__ uint16_t sBh[128 * APAD], sBl[128 * APAD];

    int bm = blockIdx.y * 128, bn = blockIdx.x * 128;
    float acc[4][4][4];
    gemm_mainloop_bf16x3(g_o, Cc, Bw, Cc, bm, bn, Cc, sAh, sAl, sBh, sBl, acc);

    int tid = threadIdx.x;
    int l = tid & 31;
    int w = tid >> 5;
    int wm = (w >> 2) * 64, wn = (w & 3) * 32;

#pragma unroll
    for (int mf = 0; mf < 4; mf++) {
#pragma unroll
        for (int half = 0; half < 2; half++) {
            int row = bm + wm + mf * 16 + (l >> 2) + half * 8;
#pragma unroll
            for (int nf = 0; nf < 4; nf++) {
                int col = bn + wn + nf * 8 + (l & 3) * 2;
                float y0 = acc[mf][nf][half * 2 + 0] + bias[col];
                float y1 = acc[mf][nf][half * 2 + 1] + bias[col + 1];
                *(float2*)(out + (size_t)row * Cc + col) = make_float2(y0, y1);
            }
        }
    }
}

// ---------------- Flash attention (causal), fp32 SIMT ----------------
#define SROW 68   // padded row stride in shared
__global__ __launch_bounds__(256) void flash_attn_kernel()
{
    extern __shared__ float sm[];
    float* Qs = sm;
    float* Ks = sm + 64 * SROW;
    float* Vs = sm + 2 * 64 * SROW;
    float* Ps = sm + 3 * 64 * SROW;

    int tid = threadIdx.x;
    int tx = tid & 15, ty = tid >> 4;
    int bh = blockIdx.y;      // b*H + h
    int qb = blockIdx.x;      // query tile index
    int b = bh / Hh, h = bh % Hh;

    const float* Qp = g_q + (size_t)bh * Nn * Dd + (size_t)qb * 64 * Dd;
    const float* Kp = g_k + (size_t)bh * Nn * Dd;
    const float* Vp = g_v + (size_t)bh * Nn * Dd;

#pragma unroll
    for (int t = 0; t < 4; t++) {
        int idx = tid + t * 256;
        int r = idx >> 4, c = (idx & 15) << 2;
        *(float4*)&Qs[r * SROW + c] = *(const float4*)(Qp + r * Dd + c);
    }

    float m[4], l[4];
    float4 o[4];
#pragma unroll
    for (int i = 0; i < 4; i++) {
        m[i] = -1e30f; l[i] = 0.0f;
        o[i] = make_float4(0.f, 0.f, 0.f, 0.f);
    }
    __syncthreads();

    for (int kb = 0; kb <= qb; kb++) {
        const float* Kt = Kp + (size_t)kb * 64 * Dd;
        const float* Vt = Vp + (size_t)kb * 64 * Dd;
#pragma unroll
        for (int t = 0; t < 4; t++) {
            int idx = tid + t * 256;
            int r = idx >> 4, c = (idx & 15) << 2;
            *(float4*)&Ks[r * SROW + c] = *(const float4*)(Kt + r * Dd + c);
            *(float4*)&Vs[r * SROW + c] = *(const float4*)(Vt + r * Dd + c);
        }
        __syncthreads();

        float s[4][4];
#pragma unroll
        for (int i = 0; i < 4; i++)
#pragma unroll
            for (int j = 0; j < 4; j++) s[i][j] = 0.0f;

#pragma unroll
        for (int d4 = 0; d4 < 16; d4++) {
            float4 qv[4], kv[4];
#pragma unroll
            for (int i = 0; i < 4; i++) qv[i] = *(float4*)&Qs[(ty * 4 + i) * SROW + d4 * 4];
#pragma unroll
            for (int j = 0; j < 4; j++) kv[j] = *(float4*)&Ks[(tx * 4 + j) * SROW + d4 * 4];
#pragma unroll
            for (int i = 0; i < 4; i++)
#pragma unroll
                for (int j = 0; j < 4; j++) {
                    s[i][j] = fmaf(qv[i].x, kv[j].x, s[i][j]);
                    s[i][j] = fmaf(qv[i].y, kv[j].y, s[i][j]);
                    s[i][j] = fmaf(qv[i].z, kv[j].z, s[i][j]);
                    s[i][j] = fmaf(qv[i].w, kv[j].w, s[i][j]);
                }
        }

        bool diag = (kb == qb);
#pragma unroll
        for (int i = 0; i < 4; i++) {
            int qg = qb * 64 + ty * 4 + i;
#pragma unroll
            for (int j = 0; j < 4; j++) {
                s[i][j] *= SCALE;
                if (diag) {
                    int kg = kb * 64 + tx * 4 + j;
                    if (kg > qg) s[i][j] = -1e30f;
                }
            }
        }

#pragma unroll
        for (int i = 0; i < 4; i++) {
            float rm = fmaxf(fmaxf(s[i][0], s[i][1]), fmaxf(s[i][2], s[i][3]));
#pragma unroll
            for (int off = 8; off >= 1; off >>= 1)
                rm = fmaxf(rm, __shfl_xor_sync(0xffffffffu, rm, off));
            float mnew = fmaxf(m[i], rm);
            float alpha = __expf(m[i] - mnew);
            float p0 = __expf(s[i][0] - mnew);
            float p1 = __expf(s[i][1] - mnew);
            float p2 = __expf(s[i][2] - mnew);
            float p3 = __expf(s[i][3] - mnew);
            float rs = p0 + p1 + p2 + p3;
#pragma unroll
            for (int off = 8; off >= 1; off >>= 1)
                rs += __shfl_xor_sync(0xffffffffu, rs, off);
            l[i] = l[i] * alpha + rs;
            o[i].x *= alpha; o[i].y *= alpha; o[i].z *= alpha; o[i].w *= alpha;
            m[i] = mnew;
            int r = ty * 4 + i;
            Ps[r * SROW + tx * 4 + 0] = p0;
            Ps[r * SROW + tx * 4 + 1] = p1;
            Ps[r * SROW + tx * 4 + 2] = p2;
            Ps[r * SROW + tx * 4 + 3] = p3;
        }
        __syncthreads();

#pragma unroll
        for (int k4 = 0; k4 < 16; k4++) {
            float4 pv[4], vv[4];
#pragma unroll
            for (int i = 0; i < 4; i++) pv[i] = *(float4*)&Ps[(ty * 4 + i) * SROW + k4 * 4];
#pragma unroll
            for (int j = 0; j < 4; j++) vv[j] = *(float4*)&Vs[(k4 * 4 + j) * SROW + tx * 4];
#pragma unroll
            for (int i = 0; i < 4; i++) {
                o[i].x = fmaf(pv[i].x, vv[0].x, o[i].x);
                o[i].x = fmaf(pv[i].y, vv[1].x, o[i].x);
                o[i].x = fmaf(pv[i].z, vv[2].x, o[i].x);
                o[i].x = fmaf(pv[i].w, vv[3].x, o[i].x);
                o[i].y = fmaf(pv[i].x, vv[0].y, o[i].y);
                o[i].y = fmaf(pv[i].y, vv[1].y, o[i].y);
                o[i].y = fmaf(pv[i].z, vv[2].y, o[i].y);
                o[i].y = fmaf(pv[i].w, vv[3].y, o[i].y);
                o[i].z = fmaf(pv[i].x, vv[0].z, o[i].z);
                o[i].z = fmaf(pv[i].y, vv[1].z, o[i].z);
                o[i].z = fmaf(pv[i].z, vv[2].z, o[i].z);
                o[i].z = fmaf(pv[i].w, vv[3].z, o[i].z);
                o[i].w = fmaf(pv[i].x, vv[0].w, o[i].w);
                o[i].w = fmaf(pv[i].y, vv[1].w, o[i].w);
                o[i].w = fmaf(pv[i].z, vv[2].w, o[i].w);
                o[i].w = fmaf(pv[i].w, vv[3].w, o[i].w);
            }
        }
        __syncthreads();
    }

#pragma unroll
    for (int i = 0; i < 4; i++) {
        float inv = 1.0f / l[i];
        int qg = qb * 64 + ty * 4 + i;
        float4 ov = make_float4(o[i].x * inv, o[i].y * inv, o[i].z * inv, o[i].w * inv);
        *(float4*)(g_o + ((size_t)(b * Nn + qg) * Hh + h) * Dd + tx * 4) = ov;
    }
}

// ---------------- launch ----------------
extern "C" void kernel_launch(void* const* d_in, const int* in_sizes, int n_in,
                              void* d_out, int out_size)
{
    (void)in_sizes; (void)n_in; (void)out_size;
    const float* x    = (const float*)d_in[0];
    const float* Wqkv = (const float*)d_in[1];
    const float* Wout = (const float*)d_in[2];
    const float* bout = (const float*)d_in[3];
    float* out = (float*)d_out;

    const int smem_attn = 4 * 64 * SROW * (int)sizeof(float); // 69632 B
    cudaFuncSetAttribute(flash_attn_kernel,
                         cudaFuncAttributeMaxDynamicSharedMemorySize, smem_attn);

    rope_init_kernel<<<(Nn * (Dd/2) + 255) / 256, 256>>>();
    qkv_mma_gemm<<<dim3(K3 / 128, Mtot / 128), 256>>>(x, Wqkv);
    flash_attn_kernel<<<dim3(Nn / 64, Bb * Hh), 256, smem_attn>>>();
    out_mma_gemm<<<dim3(Cc / 128, Mtot / 128), 256>>>(Wout, bout, out);
}

// round 7
// speedup vs baseline: 1.6259x; 1.6259x over previous
#include <cuda_runtime.h>
#include <cuda_bf16.h>
#include <math.h>
#include <stdint.h>

#define Bb 2
#define Nn 2048
#define Cc 1024
#define Hh 16
#define Dd 64
#define Mtot (Bb*Nn)     /* 4096 */
#define K3  (3*Cc)       /* 3072 */
#define SCALE 0.125f
#define SL2E 0.1803368801111244f   /* 0.125 * log2(e) */

// ---------------- scratch (static device arrays; no runtime alloc) ----------
__device__ float g_q[(size_t)Bb*Hh*Nn*Dd];   // [B,H,N,D] = [bh][pos][d]
__device__ float g_k[(size_t)Bb*Hh*Nn*Dd];
__device__ float g_v[(size_t)Bb*Hh*Nn*Dd];
__device__ float g_o[(size_t)Mtot*Cc];       // attention out, [B,N,H,D] = [4096,1024]
__device__ float g_cos[Nn*(Dd/2)];
__device__ float g_sin[Nn*(Dd/2)];

// ---------------- RoPE tables (R1 verbatim) ----------------
__global__ void rope_init_kernel() {
    int idx = blockIdx.x * blockDim.x + threadIdx.x;
    if (idx >= Nn * (Dd/2)) return;
    int n = idx / (Dd/2);
    int i = idx % (Dd/2);
    float invf = powf(10000.0f, -(float)i / (float)(Dd/2));
    float f = (float)n * invf;
    g_cos[idx] = cosf(f);
    g_sin[idx] = sinf(f);
}

// ---------------- GEMM1: qkv = x @ Wqkv, fused RoPE epilogue (R1 verbatim) --
__global__ __launch_bounds__(256) void qkv_rope_gemm(
    const float* __restrict__ A, const float* __restrict__ Bw)
{
    __shared__ float As[8][128];
    __shared__ float Bs[8][128];

    int tid = threadIdx.x;
    int bm = blockIdx.y * 128;
    int bn = blockIdx.x * 128;
    int tx = tid & 15, ty = tid >> 4;

    float acc[8][8];
#pragma unroll
    for (int i = 0; i < 8; i++)
#pragma unroll
        for (int j = 0; j < 8; j++) acc[i][j] = 0.0f;

    int arow = tid >> 1, ac4 = (tid & 1) * 4;
    int brow = tid >> 5, bc4 = (tid & 31) * 4;
    const float* Aptr = A + (size_t)(bm + arow) * Cc + ac4;
    const float* Bptr = Bw + (size_t)brow * K3 + bn + bc4;

    for (int kt = 0; kt < Cc / 8; kt++) {
        float4 av = *(const float4*)Aptr;
        As[ac4 + 0][arow] = av.x;
        As[ac4 + 1][arow] = av.y;
        As[ac4 + 2][arow] = av.z;
        As[ac4 + 3][arow] = av.w;
        *(float4*)&Bs[brow][bc4] = *(const float4*)Bptr;
        __syncthreads();

        float a[8], bb[8];
#pragma unroll
        for (int k = 0; k < 8; k++) {
            *(float4*)&a[0]  = *(const float4*)&As[k][ty * 4];
            *(float4*)&a[4]  = *(const float4*)&As[k][ty * 4 + 64];
            *(float4*)&bb[0] = *(const float4*)&Bs[k][tx * 4];
            *(float4*)&bb[4] = *(const float4*)&Bs[k][tx * 4 + 64];
#pragma unroll
            for (int i = 0; i < 8; i++)
#pragma unroll
                for (int j = 0; j < 8; j++) acc[i][j] = fmaf(a[i], bb[j], acc[i][j]);
        }
        __syncthreads();
        Aptr += 8;
        Bptr += 8 * K3;
    }

#pragma unroll
    for (int s = 0; s < 2; s++) {
#pragma unroll
        for (int i = 0; i < 4; i++) {
            int row = bm + s * 64 + ty * 4 + i;
            int b = row >> 11;
            int n = row & 2047;
#pragma unroll
            for (int t = 0; t < 2; t++) {
                int col = bn + t * 64 + tx * 4;
                int region = col >> 10;
                int cc = col & 1023;
                int h = cc >> 6;
                int dd = cc & 63;
                float y0 = acc[s * 4 + i][t * 4 + 0];
                float y1 = acc[s * 4 + i][t * 4 + 1];
                float y2 = acc[s * 4 + i][t * 4 + 2];
                float y3 = acc[s * 4 + i][t * 4 + 3];
                size_t base = ((size_t)(b * Hh + h) * Nn + n) * Dd;
                if (region == 2) {
                    float4 v4 = make_float4(y0, y1, y2, y3);
                    *(float4*)(g_v + base + dd) = v4;
                } else {
                    float* dst = (region == 0) ? g_q : g_k;
                    int i1 = dd >> 1;
                    float c0 = g_cos[n * 32 + i1],     s0 = g_sin[n * 32 + i1];
                    float c1 = g_cos[n * 32 + i1 + 1], s1 = g_sin[n * 32 + i1 + 1];
                    dst[base + i1]      = y0 * c0 - y1 * s0;
                    dst[base + i1 + 32] = y0 * s0 + y1 * c0;
                    dst[base + i1 + 1]      = y2 * c1 - y3 * s1;
                    dst[base + i1 + 1 + 32] = y2 * s1 + y3 * c1;
                }
            }
        }
    }
}

// ---------------- GEMM3: out = g_o @ Wout + bout (R1 verbatim) --------------
__global__ __launch_bounds__(256) void out_gemm(
    const float* __restrict__ Bw, const float* __restrict__ bias,
    float* __restrict__ out)
{
    __shared__ float As[8][128];
    __shared__ float Bs[8][128];

    int tid = threadIdx.x;
    int bm = blockIdx.y * 128;
    int bn = blockIdx.x * 128;
    int tx = tid & 15, ty = tid >> 4;

    float acc[8][8];
#pragma unroll
    for (int i = 0; i < 8; i++)
#pragma unroll
        for (int j = 0; j < 8; j++) acc[i][j] = 0.0f;

    int arow = tid >> 1, ac4 = (tid & 1) * 4;
    int brow = tid >> 5, bc4 = (tid & 31) * 4;
    const float* Aptr = g_o + (size_t)(bm + arow) * Cc + ac4;
    const float* Bptr = Bw + (size_t)brow * Cc + bn + bc4;

    for (int kt = 0; kt < Cc / 8; kt++) {
        float4 av = *(const float4*)Aptr;
        As[ac4 + 0][arow] = av.x;
        As[ac4 + 1][arow] = av.y;
        As[ac4 + 2][arow] = av.z;
        As[ac4 + 3][arow] = av.w;
        *(float4*)&Bs[brow][bc4] = *(const float4*)Bptr;
        __syncthreads();

        float a[8], bb[8];
#pragma unroll
        for (int k = 0; k < 8; k++) {
            *(float4*)&a[0]  = *(const float4*)&As[k][ty * 4];
            *(float4*)&a[4]  = *(const float4*)&As[k][ty * 4 + 64];
            *(float4*)&bb[0] = *(const float4*)&Bs[k][tx * 4];
            *(float4*)&bb[4] = *(const float4*)&Bs[k][tx * 4 + 64];
#pragma unroll
            for (int i = 0; i < 8; i++)
#pragma unroll
                for (int j = 0; j < 8; j++) acc[i][j] = fmaf(a[i], bb[j], acc[i][j]);
        }
        __syncthreads();
        Aptr += 8;
        Bptr += 8 * Cc;
    }

#pragma unroll
    for (int s = 0; s < 2; s++) {
#pragma unroll
        for (int i = 0; i < 4; i++) {
            int row = bm + s * 64 + ty * 4 + i;
#pragma unroll
            for (int t = 0; t < 2; t++) {
                int col = bn + t * 64 + tx * 4;
                float4 bi = *(const float4*)&bias[col];
                float4 r4 = make_float4(acc[s * 4 + i][t * 4 + 0] + bi.x,
                                        acc[s * 4 + i][t * 4 + 1] + bi.y,
                                        acc[s * 4 + i][t * 4 + 2] + bi.z,
                                        acc[s * 4 + i][t * 4 + 3] + bi.w);
                *(float4*)(out + (size_t)row * Cc + col) = r4;
            }
        }
    }
}

// ===================== Flash attention (mma.sync bf16x3) — NEW ==============
// Reads fp32 g_q/g_k/g_v ([bh][pos][d]); converts to bf16 hi/lo in smem;
// V transposed in smem to [d][pos].  128 q-rows/block, 8 warps x 16 rows,
// KV tiles of 64, single-buffered (2 syncs/tile).  Writes fp32 g_o [m][c].
#define AP 72
#define AT_SMEM 73728
// byte offsets: QH 0 (18432) QL 18432 | KH 36864 (9216) KL 46080 | VH 55296 VL 64512

__device__ __forceinline__ void mma_bf16(float* c, const uint32_t* a, const uint32_t* b) {
    asm volatile("mma.sync.aligned.m16n8k16.row.col.f32.bf16.bf16.f32 "
        "{%0,%1,%2,%3}, {%4,%5,%6,%7}, {%8,%9}, {%0,%1,%2,%3};"
        : "+f"(c[0]), "+f"(c[1]), "+f"(c[2]), "+f"(c[3])
        : "r"(a[0]), "r"(a[1]), "r"(a[2]), "r"(a[3]), "r"(b[0]), "r"(b[1]));
}
__device__ __forceinline__ void fsplit(float x, uint16_t& h, uint16_t& lo) {
    __nv_bfloat16 hb = __float2bfloat16_rn(x);
    float r = x - __bfloat162float(hb);
    __nv_bfloat16 lb = __float2bfloat16_rn(r);
    h  = *(uint16_t*)&hb;
    lo = *(uint16_t*)&lb;
}
__device__ __forceinline__ float ex2(float x) {
    float y;
    asm("ex2.approx.ftz.f32 %0, %1;" : "=f"(y) : "f"(x));
    return y;
}

__global__ __launch_bounds__(256) void flash_mma_kernel() {
    extern __shared__ char sm[];
    uint16_t* sQh = (uint16_t*)sm;
    uint16_t* sQl = (uint16_t*)(sm + 18432);
    uint16_t* sKh = (uint16_t*)(sm + 36864);
    uint16_t* sKl = (uint16_t*)(sm + 46080);
    uint16_t* sVh = (uint16_t*)(sm + 55296);
    uint16_t* sVl = (uint16_t*)(sm + 64512);

    int tid = threadIdx.x, l = tid & 31, w = tid >> 5;
    int wm = w * 16;
    int bh = blockIdx.y;
    int qb = blockIdx.x;
    int b = bh >> 4, h = bh & 15;

    // ---- Q: load fp32, split, store [r][d] ----
    const float* Qp = g_q + ((size_t)bh * Nn + qb * 128) * Dd;
#pragma unroll
    for (int i = 0; i < 8; i++) {
        int idx = tid + 256 * i;
        int r = idx >> 4, c4 = (idx & 15) * 4;
        float4 v = *(const float4*)(Qp + (size_t)r * Dd + c4);
        uint16_t h0,l0,h1,l1,h2,l2,h3,l3;
        fsplit(v.x, h0, l0); fsplit(v.y, h1, l1);
        fsplit(v.z, h2, l2); fsplit(v.w, h3, l3);
        uint32_t* ph = (uint32_t*)&sQh[r * AP + c4];
        uint32_t* pl = (uint32_t*)&sQl[r * AP + c4];
        ph[0] = (uint32_t)h0 | ((uint32_t)h1 << 16);
        ph[1] = (uint32_t)h2 | ((uint32_t)h3 << 16);
        pl[0] = (uint32_t)l0 | ((uint32_t)l1 << 16);
        pl[1] = (uint32_t)l2 | ((uint32_t)l3 << 16);
    }

    float O[8][4];
#pragma unroll
    for (int nf = 0; nf < 8; nf++)
#pragma unroll
        for (int i = 0; i < 4; i++) O[nf][i] = 0.0f;
    float mrow[2] = {-1e30f, -1e30f};
    float lsum[2] = {0.0f, 0.0f};

    const float* Kp = g_k + (size_t)bh * Nn * Dd;
    const float* Vp = g_v + (size_t)bh * Nn * Dd;

    const int ntiles = 2 * qb + 2;
    for (int t = 0; t < ntiles; t++) {
        // load K,V fp32 tiles into regs
        float4 kv4[4], vv4[4];
#pragma unroll
        for (int i = 0; i < 4; i++) {
            int idx = tid + 256 * i;
            int r = idx >> 4, c4 = (idx & 15) * 4;
            kv4[i] = *(const float4*)(Kp + (size_t)(t * 64 + r) * Dd + c4);
            vv4[i] = *(const float4*)(Vp + (size_t)(t * 64 + r) * Dd + c4);
        }
        __syncthreads();   // previous tile's smem reads done
#pragma unroll
        for (int i = 0; i < 4; i++) {
            int idx = tid + 256 * i;
            int r = idx >> 4, c4 = (idx & 15) * 4;
            // K: [pos r][d] rows
            uint16_t h0,l0,h1,l1,h2,l2,h3,l3;
            fsplit(kv4[i].x, h0, l0); fsplit(kv4[i].y, h1, l1);
            fsplit(kv4[i].z, h2, l2); fsplit(kv4[i].w, h3, l3);
            uint32_t* ph = (uint32_t*)&sKh[r * AP + c4];
            uint32_t* pl = (uint32_t*)&sKl[r * AP + c4];
            ph[0] = (uint32_t)h0 | ((uint32_t)h1 << 16);
            ph[1] = (uint32_t)h2 | ((uint32_t)h3 << 16);
            pl[0] = (uint32_t)l0 | ((uint32_t)l1 << 16);
            pl[1] = (uint32_t)l2 | ((uint32_t)l3 << 16);
            // V transposed: (r, c4+j) -> [d = c4+j][pos r]
            float vs[4] = {vv4[i].x, vv4[i].y, vv4[i].z, vv4[i].w};
#pragma unroll
            for (int j = 0; j < 4; j++) {
                uint16_t hh, ll;
                fsplit(vs[j], hh, ll);
                sVh[(c4 + j) * AP + r] = hh;
                sVl[(c4 + j) * AP + r] = ll;
            }
        }
        __syncthreads();

        // ---- S = Q K^T (bf16x3) ----
        float S[8][4];
#pragma unroll
        for (int nf = 0; nf < 8; nf++)
#pragma unroll
            for (int i = 0; i < 4; i++) S[nf][i] = 0.0f;

#pragma unroll
        for (int ks = 0; ks < 4; ks++) {
            int kc = ks * 16 + (l & 3) * 2;
            int r = wm + (l >> 2);
            uint32_t qh[4], ql[4];
            qh[0] = *(const uint32_t*)&sQh[(r    ) * AP + kc];
            qh[1] = *(const uint32_t*)&sQh[(r + 8) * AP + kc];
            qh[2] = *(const uint32_t*)&sQh[(r    ) * AP + kc + 8];
            qh[3] = *(const uint32_t*)&sQh[(r + 8) * AP + kc + 8];
            ql[0] = *(const uint32_t*)&sQl[(r    ) * AP + kc];
            ql[1] = *(const uint32_t*)&sQl[(r + 8) * AP + kc];
            ql[2] = *(const uint32_t*)&sQl[(r    ) * AP + kc + 8];
            ql[3] = *(const uint32_t*)&sQl[(r + 8) * AP + kc + 8];
#pragma unroll
            for (int nf = 0; nf < 8; nf++) {
                int n = nf * 8 + (l >> 2);
                uint32_t kh2[2], kl2[2];
                kh2[0] = *(const uint32_t*)&sKh[n * AP + kc];
                kh2[1] = *(const uint32_t*)&sKh[n * AP + kc + 8];
                kl2[0] = *(const uint32_t*)&sKl[n * AP + kc];
                kl2[1] = *(const uint32_t*)&sKl[n * AP + kc + 8];
                mma_bf16(S[nf], qh, kh2);
                mma_bf16(S[nf], ql, kh2);
                mma_bf16(S[nf], qh, kl2);
            }
        }

        // ---- scale + causal mask ----
        bool domask = (t >= 2 * qb);
#pragma unroll
        for (int nf = 0; nf < 8; nf++)
#pragma unroll
            for (int idx = 0; idx < 4; idx++) {
                float v = S[nf][idx] * SL2E;
                if (domask) {
                    int h2 = idx >> 1, ci = idx & 1;
                    int qg = qb * 128 + wm + (l >> 2) + h2 * 8;
                    int kg = t * 64 + nf * 8 + (l & 3) * 2 + ci;
                    if (kg > qg) v = -1e30f;
                }
                S[nf][idx] = v;
            }

        // ---- online softmax (base-2; quad shfl across lanes 1,2) ----
#pragma unroll
        for (int h2 = 0; h2 < 2; h2++) {
            float mx = -1e30f;
#pragma unroll
            for (int nf = 0; nf < 8; nf++)
                mx = fmaxf(mx, fmaxf(S[nf][h2*2], S[nf][h2*2+1]));
            mx = fmaxf(mx, __shfl_xor_sync(0xffffffffu, mx, 1));
            mx = fmaxf(mx, __shfl_xor_sync(0xffffffffu, mx, 2));
            float mnew = fmaxf(mrow[h2], mx);
            float scl = ex2(mrow[h2] - mnew);
            float sum = 0.0f;
#pragma unroll
            for (int nf = 0; nf < 8; nf++) {
                float p0 = ex2(S[nf][h2*2]   - mnew);
                float p1 = ex2(S[nf][h2*2+1] - mnew);
                S[nf][h2*2]   = p0;
                S[nf][h2*2+1] = p1;
                sum += p0 + p1;
            }
            sum += __shfl_xor_sync(0xffffffffu, sum, 1);
            sum += __shfl_xor_sync(0xffffffffu, sum, 2);
            lsum[h2] = lsum[h2] * scl + sum;
            mrow[h2] = mnew;
#pragma unroll
            for (int nf = 0; nf < 8; nf++) {
                O[nf][h2*2]   *= scl;
                O[nf][h2*2+1] *= scl;
            }
        }

        // ---- O += P V  (P in regs as bf16x2; V^T from smem) ----
#pragma unroll
        for (int ks = 0; ks < 4; ks++) {
            uint32_t ph[4], pl[4];
#pragma unroll
            for (int half = 0; half < 2; half++) {
#pragma unroll
                for (int rr = 0; rr < 2; rr++) {
                    float v0 = S[2*ks + half][rr*2];
                    float v1 = S[2*ks + half][rr*2 + 1];
                    uint16_t a0, b0, a1, b1;
                    fsplit(v0, a0, b0);
                    fsplit(v1, a1, b1);
                    ph[half*2 + rr] = (uint32_t)a0 | ((uint32_t)a1 << 16);
                    pl[half*2 + rr] = (uint32_t)b0 | ((uint32_t)b1 << 16);
                }
            }
            int kc = ks * 16 + (l & 3) * 2;
#pragma unroll
            for (int nf = 0; nf < 8; nf++) {
                int n = nf * 8 + (l >> 2);
                uint32_t vh2[2], vl2[2];
                vh2[0] = *(const uint32_t*)&sVh[n * AP + kc];
                vh2[1] = *(const uint32_t*)&sVh[n * AP + kc + 8];
                vl2[0] = *(const uint32_t*)&sVl[n * AP + kc];
                vl2[1] = *(const uint32_t*)&sVl[n * AP + kc + 8];
                mma_bf16(O[nf], ph, vh2);
                mma_bf16(O[nf], pl, vh2);
                mma_bf16(O[nf], ph, vl2);
            }
        }
    }

    // ---- finalize: O /= l, store fp32 to g_o [b*Nn+q][h*64+d] ----
    float inv[2] = {1.0f / lsum[0], 1.0f / lsum[1]};
#pragma unroll
    for (int nf = 0; nf < 8; nf++)
#pragma unroll
        for (int h2 = 0; h2 < 2; h2++) {
            int q = qb * 128 + wm + (l >> 2) + h2 * 8;
            int col = h * 64 + nf * 8 + (l & 3) * 2;
            size_t o = (size_t)(b * Nn + q) * Cc + col;
            *(float2*)(g_o + o) = make_float2(O[nf][h2*2] * inv[h2],
                                              O[nf][h2*2+1] * inv[h2]);
        }
}

// ---------------- launch ----------------------------------------------------
extern "C" void kernel_launch(void* const* d_in, const int* in_sizes, int n_in,
                              void* d_out, int out_size)
{
    (void)in_sizes; (void)n_in; (void)out_size;
    const float* x    = (const float*)d_in[0];
    const float* Wqkv = (const float*)d_in[1];
    const float* Wout = (const float*)d_in[2];
    const float* bout = (const float*)d_in[3];
    float* out = (float*)d_out;

    cudaFuncSetAttribute(flash_mma_kernel,
                         cudaFuncAttributeMaxDynamicSharedMemorySize, AT_SMEM);

    rope_init_kernel<<<(Nn * (Dd/2) + 255) / 256, 256>>>();
    qkv_rope_gemm<<<dim3(K3 / 128, Mtot / 128), 256>>>(x, Wqkv);
    flash_mma_kernel<<<dim3(Nn / 128, Bb * Hh), 256, AT_SMEM>>>();
    out_gemm<<<dim3(Cc / 128, Mtot / 128), 256>>>(Wout, bout, out);
}

// round 9
// speedup vs baseline: 2.5438x; 1.5645x over previous
#include <cuda_runtime.h>
#include <cuda_bf16.h>
#include <math.h>
#include <stdint.h>

#define Bb 2
#define Nn 2048
#define Cc 1024
#define Hh 16
#define Dd 64
#define Mtot (Bb*Nn)     /* 4096 */
#define K3  (3*Cc)       /* 3072 */
#define SL2E 0.1803368801111244f   /* 0.125 * log2(e) */

// ---------------- scratch ----------------------------------------------------
__device__ __align__(16) uint16_t g_wqh[(size_t)K3*Cc], g_wql[(size_t)K3*Cc]; // WqkvT [n][k]
__device__ __align__(16) uint16_t g_woh[(size_t)Cc*Cc], g_wol[(size_t)Cc*Cc]; // WoutT [n][k]
__device__ float g_q[(size_t)Bb*Hh*Nn*Dd];   // [bh][pos][d]
__device__ float g_k[(size_t)Bb*Hh*Nn*Dd];
__device__ float g_v[(size_t)Bb*Hh*Nn*Dd];
__device__ float g_o[(size_t)Mtot*Cc];       // [b*Nn+q][h*64+d]
__device__ float g_cos[Nn*32], g_sin[Nn*32];

// ---------------- helpers ----------------------------------------------------
__device__ __forceinline__ void mma_bf16(float* c, const uint32_t* a, const uint32_t* b) {
    asm volatile("mma.sync.aligned.m16n8k16.row.col.f32.bf16.bf16.f32 "
        "{%0,%1,%2,%3}, {%4,%5,%6,%7}, {%8,%9}, {%0,%1,%2,%3};"
        : "+f"(c[0]), "+f"(c[1]), "+f"(c[2]), "+f"(c[3])
        : "r"(a[0]), "r"(a[1]), "r"(a[2]), "r"(a[3]), "r"(b[0]), "r"(b[1]));
}
__device__ __forceinline__ void fsplit(float x, uint16_t& h, uint16_t& lo) {
    __nv_bfloat16 hb = __float2bfloat16_rn(x);
    float r = x - __bfloat162float(hb);
    __nv_bfloat16 lb = __float2bfloat16_rn(r);
    h  = *(uint16_t*)&hb;
    lo = *(uint16_t*)&lb;
}
__device__ __forceinline__ float ex2(float x) {
    float y;
    asm("ex2.approx.ftz.f32 %0, %1;" : "=f"(y) : "f"(x));
    return y;
}

// ---------------- init kernels -----------------------------------------------
__global__ void rope_init_kernel() {
    int idx = blockIdx.x * blockDim.x + threadIdx.x;
    if (idx >= Nn * 32) return;
    int n = idx >> 5, i = idx & 31;
    float invf = powf(10000.0f, -(float)i / 32.0f);
    float f = (float)n * invf;
    g_cos[idx] = cosf(f);
    g_sin[idx] = sinf(f);
}

// W [R][C] -> T [C][R] (split hi/lo).  Destination symbols referenced in
// DEVICE code (selected by `which`) — never passed as host-side kernel args
// (on GB300/ATS a host-passed __device__ symbol silently writes host shadow
// memory: the R4-R8 bug).
__global__ void transpose_split_kernel(const float* __restrict__ W,
                                       int R, int C, int which) {
    uint16_t* __restrict__ Th = which ? g_woh : g_wqh;
    uint16_t* __restrict__ Tl = which ? g_wol : g_wql;
    __shared__ float tile[32][33];
    int bx = blockIdx.x * 32, by = blockIdx.y * 32;
    int tx = threadIdx.x, ty = threadIdx.y;
#pragma unroll
    for (int i = 0; i < 4; i++)
        tile[ty + 8*i][tx] = W[(size_t)(by + ty + 8*i) * C + bx + tx];
    __syncthreads();
#pragma unroll
    for (int i = 0; i < 4; i++) {
        float v = tile[tx][ty + 8*i];
        uint16_t h, l;
        fsplit(v, h, l);
        size_t o = (size_t)(bx + ty + 8*i) * R + by + tx;
        Th[o] = h; Tl[o] = l;
    }
}

// ============ bf16x3 GEMM core: A fp32 (split in-kernel), B pre-split ========
// 128x128 tile, BK=32, 256 threads (warps 2x4, warp tile 64x32),
// double-buffered smem, 1 sync/iter.
#define GEMM_SMEM 81920
#define GP 40

__device__ __forceinline__ void gemm_core2(
    const float* __restrict__ A,
    const uint16_t* __restrict__ Bh, const uint16_t* __restrict__ Bl,
    int bm, int bn, char* sm, float acc[4][4][4])
{
    int tid = threadIdx.x, l = tid & 31, w = tid >> 5;
    int wm = (w >> 2) * 64, wn = (w & 3) * 32;

#pragma unroll
    for (int mf = 0; mf < 4; mf++)
#pragma unroll
        for (int nf = 0; nf < 4; nf++)
#pragma unroll
            for (int i = 0; i < 4; i++) acc[mf][nf][i] = 0.0f;

    float4 rA[4];
    uint4 rBh[2], rBl[2];

    auto load_regs = [&](int kt) {
#pragma unroll
        for (int i = 0; i < 4; i++) {
            int ch = tid + 256 * i;
            int r = ch >> 3, g = ch & 7;
            rA[i] = *(const float4*)(A + (size_t)(bm + r) * Cc + kt * 32 + g * 4);
        }
#pragma unroll
        for (int i = 0; i < 2; i++) {
            int ch = tid + 256 * i;
            int r = ch >> 2, g = ch & 3;
            size_t off = (size_t)(bn + r) * Cc + kt * 32 + g * 8;
            rBh[i] = *(const uint4*)(Bh + off);
            rBl[i] = *(const uint4*)(Bl + off);
        }
    };
    auto store_smem = [&](int st) {
        char* s0 = sm + st * 40960;
#pragma unroll
        for (int i = 0; i < 4; i++) {
            int ch = tid + 256 * i;
            int r = ch >> 3, g = ch & 7;
            uint16_t h0,l0,h1,l1,h2,l2,h3,l3;
            fsplit(rA[i].x, h0, l0); fsplit(rA[i].y, h1, l1);
            fsplit(rA[i].z, h2, l2); fsplit(rA[i].w, h3, l3);
            uint2 hp = make_uint2((uint32_t)h0 | ((uint32_t)h1 << 16),
                                  (uint32_t)h2 | ((uint32_t)h3 << 16));
            uint2 lp = make_uint2((uint32_t)l0 | ((uint32_t)l1 << 16),
                                  (uint32_t)l2 | ((uint32_t)l3 << 16));
            *(uint2*)(s0 + r * 80 + g * 8)          = hp;
            *(uint2*)(s0 + 10240 + r * 80 + g * 8)  = lp;
        }
#pragma unroll
        for (int i = 0; i < 2; i++) {
            int ch = tid + 256 * i;
            int r = ch >> 2, g = ch & 3;
            *(uint4*)(s0 + 20480 + r * 80 + g * 16) = rBh[i];
            *(uint4*)(s0 + 30720 + r * 80 + g * 16) = rBl[i];
        }
    };

    load_regs(0);
    for (int kt = 0; kt < 32; kt++) {
        store_smem(kt & 1);
        __syncthreads();
        if (kt + 1 < 32) load_regs(kt + 1);

        const uint16_t* sAh = (const uint16_t*)(sm + (kt & 1) * 40960);
        const uint16_t* sAl = sAh + 5120;
        const uint16_t* sBh = sAh + 10240;
        const uint16_t* sBl = sAh + 15360;
#pragma unroll
        for (int ks = 0; ks < 2; ks++) {
            int kc = ks * 16 + (l & 3) * 2;
            int r0 = wm + (l >> 2);
            uint32_t ah[4][4], al[4][4];
#pragma unroll
            for (int mf = 0; mf < 4; mf++) {
                int r = r0 + mf * 16;
                ah[mf][0] = *(const uint32_t*)&sAh[(r    ) * GP + kc];
                ah[mf][1] = *(const uint32_t*)&sAh[(r + 8) * GP + kc];
                ah[mf][2] = *(const uint32_t*)&sAh[(r    ) * GP + kc + 8];
                ah[mf][3] = *(const uint32_t*)&sAh[(r + 8) * GP + kc + 8];
                al[mf][0] = *(const uint32_t*)&sAl[(r    ) * GP + kc];
                al[mf][1] = *(const uint32_t*)&sAl[(r + 8) * GP + kc];
                al[mf][2] = *(const uint32_t*)&sAl[(r    ) * GP + kc + 8];
                al[mf][3] = *(const uint32_t*)&sAl[(r + 8) * GP + kc + 8];
            }
#pragma unroll
            for (int nf = 0; nf < 4; nf++) {
                int n = wn + nf * 8 + (l >> 2);
                uint32_t bh2[2], bl2[2];
                bh2[0] = *(const uint32_t*)&sBh[n * GP + kc];
                bh2[1] = *(const uint32_t*)&sBh[n * GP + kc + 8];
                bl2[0] = *(const uint32_t*)&sBl[n * GP + kc];
                bl2[1] = *(const uint32_t*)&sBl[n * GP + kc + 8];
#pragma unroll
                for (int mf = 0; mf < 4; mf++) {
                    mma_bf16(acc[mf][nf], ah[mf], bh2);
                    mma_bf16(acc[mf][nf], al[mf], bh2);
                    mma_bf16(acc[mf][nf], ah[mf], bl2);
                }
            }
        }
    }
}

// ---------------- GEMM1: qkv + RoPE epilogue ---------------------------------
__global__ __launch_bounds__(256) void qkv_mma_gemm(const float* __restrict__ x) {
    extern __shared__ char sm[];
    int bm = blockIdx.y * 128, bn = blockIdx.x * 128;
    float acc[4][4][4];
    gemm_core2(x, g_wqh, g_wql, bm, bn, sm, acc);

    int tid = threadIdx.x, l = tid & 31, w = tid >> 5;
    int wm = (w >> 2) * 64, wn = (w & 3) * 32;

#pragma unroll
    for (int mf = 0; mf < 4; mf++) {
#pragma unroll
        for (int half = 0; half < 2; half++) {
            int row = bm + wm + mf * 16 + (l >> 2) + half * 8;
            int b = row >> 11;
            int tok = row & (Nn - 1);
#pragma unroll
            for (int nf = 0; nf < 4; nf++) {
                int col = bn + wn + nf * 8 + (l & 3) * 2;   // even
                float y0 = acc[mf][nf][half * 2 + 0];
                float y1 = acc[mf][nf][half * 2 + 1];
                int region = col >> 10;
                int cc = col & 1023;
                int h = cc >> 6;
                int dd = cc & 63;
                size_t base = ((size_t)(b * Hh + h) * Nn + tok) * Dd;
                if (region == 2) {
                    *(float2*)(g_v + base + dd) = make_float2(y0, y1);
                } else {
                    float* dst = region ? g_k : g_q;
                    int i1 = dd >> 1;
                    float cs = g_cos[tok * 32 + i1];
                    float sn = g_sin[tok * 32 + i1];
                    dst[base + i1]      = y0 * cs - y1 * sn;
                    dst[base + i1 + 32] = y0 * sn + y1 * cs;
                }
            }
        }
    }
}

// ---------------- GEMM3: out = g_o @ WoutT + bias ----------------------------
__global__ __launch_bounds__(256) void out_mma_gemm(const float* __restrict__ bias,
                                                    float* __restrict__ out) {
    extern __shared__ char sm[];
    int bm = blockIdx.y * 128, bn = blockIdx.x * 128;
    float acc[4][4][4];
    gemm_core2(g_o, g_woh, g_wol, bm, bn, sm, acc);

    int tid = threadIdx.x, l = tid & 31, w = tid >> 5;
    int wm = (w >> 2) * 64, wn = (w & 3) * 32;

#pragma unroll
    for (int mf = 0; mf < 4; mf++) {
#pragma unroll
        for (int half = 0; half < 2; half++) {
            int row = bm + wm + mf * 16 + (l >> 2) + half * 8;
#pragma unroll
            for (int nf = 0; nf < 4; nf++) {
                int col = bn + wn + nf * 8 + (l & 3) * 2;
                float y0 = acc[mf][nf][half * 2 + 0] + bias[col];
                float y1 = acc[mf][nf][half * 2 + 1] + bias[col + 1];
                *(float2*)(out + (size_t)row * Cc + col) = make_float2(y0, y1);
            }
        }
    }
}

// ===================== Flash attention (R7 verbatim, proven) =================
#define AP 72
#define AT_SMEM 73728

__global__ __launch_bounds__(256) void flash_mma_kernel() {
    extern __shared__ char sm[];
    uint16_t* sQh = (uint16_t*)sm;
    uint16_t* sQl = (uint16_t*)(sm + 18432);
    uint16_t* sKh = (uint16_t*)(sm + 36864);
    uint16_t* sKl = (uint16_t*)(sm + 46080);
    uint16_t* sVh = (uint16_t*)(sm + 55296);
    uint16_t* sVl = (uint16_t*)(sm + 64512);

    int tid = threadIdx.x, l = tid & 31, w = tid >> 5;
    int wm = w * 16;
    int bh = blockIdx.y;
    int qb = blockIdx.x;
    int b = bh >> 4, h = bh & 15;

    const float* Qp = g_q + ((size_t)bh * Nn + qb * 128) * Dd;
#pragma unroll
    for (int i = 0; i < 8; i++) {
        int idx = tid + 256 * i;
        int r = idx >> 4, c4 = (idx & 15) * 4;
        float4 v = *(const float4*)(Qp + (size_t)r * Dd + c4);
        uint16_t h0,l0,h1,l1,h2,l2,h3,l3;
        fsplit(v.x, h0, l0); fsplit(v.y, h1, l1);
        fsplit(v.z, h2, l2); fsplit(v.w, h3, l3);
        uint32_t* ph = (uint32_t*)&sQh[r * AP + c4];
        uint32_t* pl = (uint32_t*)&sQl[r * AP + c4];
        ph[0] = (uint32_t)h0 | ((uint32_t)h1 << 16);
        ph[1] = (uint32_t)h2 | ((uint32_t)h3 << 16);
        pl[0] = (uint32_t)l0 | ((uint32_t)l1 << 16);
        pl[1] = (uint32_t)l2 | ((uint32_t)l3 << 16);
    }

    float O[8][4];
#pragma unroll
    for (int nf = 0; nf < 8; nf++)
#pragma unroll
        for (int i = 0; i < 4; i++) O[nf][i] = 0.0f;
    float mrow[2] = {-1e30f, -1e30f};
    float lsum[2] = {0.0f, 0.0f};

    const float* Kp = g_k + (size_t)bh * Nn * Dd;
    const float* Vp = g_v + (size_t)bh * Nn * Dd;

    const int ntiles = 2 * qb + 2;
    for (int t = 0; t < ntiles; t++) {
        float4 kv4[4], vv4[4];
#pragma unroll
        for (int i = 0; i < 4; i++) {
            int idx = tid + 256 * i;
            int r = idx >> 4, c4 = (idx & 15) * 4;
            kv4[i] = *(const float4*)(Kp + (size_t)(t * 64 + r) * Dd + c4);
            vv4[i] = *(const float4*)(Vp + (size_t)(t * 64 + r) * Dd + c4);
        }
        __syncthreads();
#pragma unroll
        for (int i = 0; i < 4; i++) {
            int idx = tid + 256 * i;
            int r = idx >> 4, c4 = (idx & 15) * 4;
            uint16_t h0,l0,h1,l1,h2,l2,h3,l3;
            fsplit(kv4[i].x, h0, l0); fsplit(kv4[i].y, h1, l1);
            fsplit(kv4[i].z, h2, l2); fsplit(kv4[i].w, h3, l3);
            uint32_t* ph = (uint32_t*)&sKh[r * AP + c4];
            uint32_t* pl = (uint32_t*)&sKl[r * AP + c4];
            ph[0] = (uint32_t)h0 | ((uint32_t)h1 << 16);
            ph[1] = (uint32_t)h2 | ((uint32_t)h3 << 16);
            pl[0] = (uint32_t)l0 | ((uint32_t)l1 << 16);
            pl[1] = (uint32_t)l2 | ((uint32_t)l3 << 16);
            float vs[4] = {vv4[i].x, vv4[i].y, vv4[i].z, vv4[i].w};
#pragma unroll
            for (int j = 0; j < 4; j++) {
                uint16_t hh, ll;
                fsplit(vs[j], hh, ll);
                sVh[(c4 + j) * AP + r] = hh;
                sVl[(c4 + j) * AP + r] = ll;
            }
        }
        __syncthreads();

        float S[8][4];
#pragma unroll
        for (int nf = 0; nf < 8; nf++)
#pragma unroll
            for (int i = 0; i < 4; i++) S[nf][i] = 0.0f;

#pragma unroll
        for (int ks = 0; ks < 4; ks++) {
            int kc = ks * 16 + (l & 3) * 2;
            int r = wm + (l >> 2);
            uint32_t qh[4], ql[4];
            qh[0] = *(const uint32_t*)&sQh[(r    ) * AP + kc];
            qh[1] = *(const uint32_t*)&sQh[(r + 8) * AP + kc];
            qh[2] = *(const uint32_t*)&sQh[(r    ) * AP + kc + 8];
            qh[3] = *(const uint32_t*)&sQh[(r + 8) * AP + kc + 8];
            ql[0] = *(const uint32_t*)&sQl[(r    ) * AP + kc];
            ql[1] = *(const uint32_t*)&sQl[(r + 8) * AP + kc];
            ql[2] = *(const uint32_t*)&sQl[(r    ) * AP + kc + 8];
            ql[3] = *(const uint32_t*)&sQl[(r + 8) * AP + kc + 8];
#pragma unroll
            for (int nf = 0; nf < 8; nf++) {
                int n = nf * 8 + (l >> 2);
                uint32_t kh2[2], kl2[2];
                kh2[0] = *(const uint32_t*)&sKh[n * AP + kc];
                kh2[1] = *(const uint32_t*)&sKh[n * AP + kc + 8];
                kl2[0] = *(const uint32_t*)&sKl[n * AP + kc];
                kl2[1] = *(const uint32_t*)&sKl[n * AP + kc + 8];
                mma_bf16(S[nf], qh, kh2);
                mma_bf16(S[nf], ql, kh2);
                mma_bf16(S[nf], qh, kl2);
            }
        }

        bool domask = (t >= 2 * qb);
#pragma unroll
        for (int nf = 0; nf < 8; nf++)
#pragma unroll
            for (int idx = 0; idx < 4; idx++) {
                float v = S[nf][idx] * SL2E;
                if (domask) {
                    int h2 = idx >> 1, ci = idx & 1;
                    int qg = qb * 128 + wm + (l >> 2) + h2 * 8;
                    int kg = t * 64 + nf * 8 + (l & 3) * 2 + ci;
                    if (kg > qg) v = -1e30f;
                }
                S[nf][idx] = v;
            }

#pragma unroll
        for (int h2 = 0; h2 < 2; h2++) {
            float mx = -1e30f;
#pragma unroll
            for (int nf = 0; nf < 8; nf++)
                mx = fmaxf(mx, fmaxf(S[nf][h2*2], S[nf][h2*2+1]));
            mx = fmaxf(mx, __shfl_xor_sync(0xffffffffu, mx, 1));
            mx = fmaxf(mx, __shfl_xor_sync(0xffffffffu, mx, 2));
            float mnew = fmaxf(mrow[h2], mx);
            float scl = ex2(mrow[h2] - mnew);
            float sum = 0.0f;
#pragma unroll
            for (int nf = 0; nf < 8; nf++) {
                float p0 = ex2(S[nf][h2*2]   - mnew);
                float p1 = ex2(S[nf][h2*2+1] - mnew);
                S[nf][h2*2]   = p0;
                S[nf][h2*2+1] = p1;
                sum += p0 + p1;
            }
            sum += __shfl_xor_sync(0xffffffffu, sum, 1);
            sum += __shfl_xor_sync(0xffffffffu, sum, 2);
            lsum[h2] = lsum[h2] * scl + sum;
            mrow[h2] = mnew;
#pragma unroll
            for (int nf = 0; nf < 8; nf++) {
                O[nf][h2*2]   *= scl;
                O[nf][h2*2+1] *= scl;
            }
        }

#pragma unroll
        for (int ks = 0; ks < 4; ks++) {
            uint32_t ph[4], pl[4];
#pragma unroll
            for (int half = 0; half < 2; half++) {
#pragma unroll
                for (int rr = 0; rr < 2; rr++) {
                    float v0 = S[2*ks + half][rr*2];
                    float v1 = S[2*ks + half][rr*2 + 1];
                    uint16_t a0, b0, a1, b1;
                    fsplit(v0, a0, b0);
                    fsplit(v1, a1, b1);
                    ph[half*2 + rr] = (uint32_t)a0 | ((uint32_t)a1 << 16);
                    pl[half*2 + rr] = (uint32_t)b0 | ((uint32_t)b1 << 16);
                }
            }
            int kc = ks * 16 + (l & 3) * 2;
#pragma unroll
            for (int nf = 0; nf < 8; nf++) {
                int n = nf * 8 + (l >> 2);
                uint32_t vh2[2], vl2[2];
                vh2[0] = *(const uint32_t*)&sVh[n * AP + kc];
                vh2[1] = *(const uint32_t*)&sVh[n * AP + kc + 8];
                vl2[0] = *(const uint32_t*)&sVl[n * AP + kc];
                vl2[1] = *(const uint32_t*)&sVl[n * AP + kc + 8];
                mma_bf16(O[nf], ph, vh2);
                mma_bf16(O[nf], pl, vh2);
                mma_bf16(O[nf], ph, vl2);
            }
        }
    }

    float inv[2] = {1.0f / lsum[0], 1.0f / lsum[1]};
#pragma unroll
    for (int nf = 0; nf < 8; nf++)
#pragma unroll
        for (int h2 = 0; h2 < 2; h2++) {
            int q = qb * 128 + wm + (l >> 2) + h2 * 8;
            int col = h * 64 + nf * 8 + (l & 3) * 2;
            size_t o = (size_t)(b * Nn + q) * Cc + col;
            *(float2*)(g_o + o) = make_float2(O[nf][h2*2] * inv[h2],
                                              O[nf][h2*2+1] * inv[h2]);
        }
}

// ---------------- launch -----------------------------------------------------
extern "C" void kernel_launch(void* const* d_in, const int* in_sizes, int n_in,
                              void* d_out, int out_size)
{
    (void)in_sizes; (void)n_in; (void)out_size;
    const float* x    = (const float*)d_in[0];
    const float* Wqkv = (const float*)d_in[1];
    const float* Wout = (const float*)d_in[2];
    const float* bout = (const float*)d_in[3];
    float* out = (float*)d_out;

    cudaFuncSetAttribute(qkv_mma_gemm, cudaFuncAttributeMaxDynamicSharedMemorySize, GEMM_SMEM);
    cudaFuncSetAttribute(out_mma_gemm, cudaFuncAttributeMaxDynamicSharedMemorySize, GEMM_SMEM);
    cudaFuncSetAttribute(flash_mma_kernel, cudaFuncAttributeMaxDynamicSharedMemorySize, AT_SMEM);

    rope_init_kernel<<<(Nn * 32 + 255) / 256, 256>>>();
    transpose_split_kernel<<<dim3(K3 / 32, Cc / 32), dim3(32, 8)>>>(Wqkv, Cc, K3, 0);
    transpose_split_kernel<<<dim3(Cc / 32, Cc / 32), dim3(32, 8)>>>(Wout, Cc, Cc, 1);
    qkv_mma_gemm<<<dim3(K3 / 128, Mtot / 128), 256, GEMM_SMEM>>>(x);
    flash_mma_kernel<<<dim3(Nn / 128, Bb * Hh), 256, AT_SMEM>>>();
    out_mma_gemm<<<dim3(Cc / 128, Mtot / 128), 256, GEMM_SMEM>>>(bout, out);
}

// round 10
// speedup vs baseline: 2.7213x; 1.0698x over previous
#include <cuda_runtime.h>
#include <cuda_bf16.h>
#include <math.h>
#include <stdint.h>

#define Bb 2
#define Nn 2048
#define Cc 1024
#define Hh 16
#define Dd 64
#define Mtot (Bb*Nn)     /* 4096 */
#define K3  (3*Cc)       /* 3072 */
#define SL2E 0.1803368801111244f   /* 0.125 * log2(e) */

// ---------------- scratch ----------------------------------------------------
__device__ __align__(16) uint16_t g_wqh[(size_t)K3*Cc], g_wql[(size_t)K3*Cc]; // WqkvT [n][k]
__device__ __align__(16) uint16_t g_woh[(size_t)Cc*Cc], g_wol[(size_t)Cc*Cc]; // WoutT [n][k]
__device__ float g_q[(size_t)Bb*Hh*Nn*Dd];   // [bh][pos][d]
__device__ float g_k[(size_t)Bb*Hh*Nn*Dd];
__device__ float g_v[(size_t)Bb*Hh*Nn*Dd];
__device__ float g_o[(size_t)Mtot*Cc];       // [b*Nn+q][h*64+d]
__device__ float g_cos[Nn*32], g_sin[Nn*32];

// ---------------- helpers ----------------------------------------------------
__device__ __forceinline__ uint32_t smem_u32(const void* p) {
    uint32_t a;
    asm("{ .reg .u64 t; cvta.to.shared.u64 t, %1; cvt.u32.u64 %0, t; }" : "=r"(a) : "l"(p));
    return a;
}
__device__ __forceinline__ void ldsm4(uint32_t* r, uint32_t addr) {
    asm volatile("ldmatrix.sync.aligned.m8n8.x4.shared.b16 {%0,%1,%2,%3}, [%4];"
        : "=r"(r[0]), "=r"(r[1]), "=r"(r[2]), "=r"(r[3]) : "r"(addr));
}
__device__ __forceinline__ void mma_bf16(float* c, const uint32_t* a, const uint32_t* b) {
    asm volatile("mma.sync.aligned.m16n8k16.row.col.f32.bf16.bf16.f32 "
        "{%0,%1,%2,%3}, {%4,%5,%6,%7}, {%8,%9}, {%0,%1,%2,%3};"
        : "+f"(c[0]), "+f"(c[1]), "+f"(c[2]), "+f"(c[3])
        : "r"(a[0]), "r"(a[1]), "r"(a[2]), "r"(a[3]), "r"(b[0]), "r"(b[1]));
}
__device__ __forceinline__ void fsplit(float x, uint16_t& h, uint16_t& lo) {
    __nv_bfloat16 hb = __float2bfloat16_rn(x);
    float r = x - __bfloat162float(hb);
    __nv_bfloat16 lb = __float2bfloat16_rn(r);
    h  = *(uint16_t*)&hb;
    lo = *(uint16_t*)&lb;
}
__device__ __forceinline__ float ex2(float x) {
    float y;
    asm("ex2.approx.ftz.f32 %0, %1;" : "=f"(y) : "f"(x));
    return y;
}

// ---------------- init kernels -----------------------------------------------
__global__ void rope_init_kernel() {
    int idx = blockIdx.x * blockDim.x + threadIdx.x;
    if (idx >= Nn * 32) return;
    int n = idx >> 5, i = idx & 31;
    float invf = powf(10000.0f, -(float)i / 32.0f);
    float f = (float)n * invf;
    g_cos[idx] = cosf(f);
    g_sin[idx] = sinf(f);
}

// W [R][C] -> T [C][R] (split hi/lo).  Destination symbols referenced in
// DEVICE code only (GB300/ATS trap: host-passed __device__ symbol writes host
// shadow memory silently).
__global__ void transpose_split_kernel(const float* __restrict__ W,
                                       int R, int C, int which) {
    uint16_t* __restrict__ Th = which ? g_woh : g_wqh;
    uint16_t* __restrict__ Tl = which ? g_wol : g_wql;
    __shared__ float tile[32][33];
    int bx = blockIdx.x * 32, by = blockIdx.y * 32;
    int tx = threadIdx.x, ty = threadIdx.y;
#pragma unroll
    for (int i = 0; i < 4; i++)
        tile[ty + 8*i][tx] = W[(size_t)(by + ty + 8*i) * C + bx + tx];
    __syncthreads();
#pragma unroll
    for (int i = 0; i < 4; i++) {
        float v = tile[tx][ty + 8*i];
        uint16_t h, l;
        fsplit(v, h, l);
        size_t o = (size_t)(bx + ty + 8*i) * R + by + tx;
        Th[o] = h; Tl[o] = l;
    }
}

// ============ bf16x3 GEMM core: A fp32 (split in-kernel), B pre-split ========
// 128x128 tile, BK=32, 256 threads (warps 2x4, warp tile 64x32),
// double-buffered smem, 1 sync/iter, ldmatrix fragment loads.
#define GEMM_SMEM 81920
#define GP 40

__device__ __forceinline__ void gemm_core2(
    const float* __restrict__ A,
    const uint16_t* __restrict__ Bh, const uint16_t* __restrict__ Bl,
    int bm, int bn, char* sm, float acc[4][4][4])
{
    int tid = threadIdx.x, l = tid & 31, w = tid >> 5;
    int wm = (w >> 2) * 64, wn = (w & 3) * 32;
    uint32_t sb0 = smem_u32(sm);

#pragma unroll
    for (int mf = 0; mf < 4; mf++)
#pragma unroll
        for (int nf = 0; nf < 4; nf++)
#pragma unroll
            for (int i = 0; i < 4; i++) acc[mf][nf][i] = 0.0f;

    float4 rA[4];
    uint4 rBh[2], rBl[2];

    auto load_regs = [&](int kt) {
#pragma unroll
        for (int i = 0; i < 4; i++) {
            int ch = tid + 256 * i;
            int r = ch >> 3, g = ch & 7;
            rA[i] = *(const float4*)(A + (size_t)(bm + r) * Cc + kt * 32 + g * 4);
        }
#pragma unroll
        for (int i = 0; i < 2; i++) {
            int ch = tid + 256 * i;
            int r = ch >> 2, g = ch & 3;
            size_t off = (size_t)(bn + r) * Cc + kt * 32 + g * 8;
            rBh[i] = *(const uint4*)(Bh + off);
            rBl[i] = *(const uint4*)(Bl + off);
        }
    };
    auto store_smem = [&](int st) {
        char* s0 = sm + st * 40960;
#pragma unroll
        for (int i = 0; i < 4; i++) {
            int ch = tid + 256 * i;
            int r = ch >> 3, g = ch & 7;
            uint16_t h0,l0,h1,l1,h2,l2,h3,l3;
            fsplit(rA[i].x, h0, l0); fsplit(rA[i].y, h1, l1);
            fsplit(rA[i].z, h2, l2); fsplit(rA[i].w, h3, l3);
            uint2 hp = make_uint2((uint32_t)h0 | ((uint32_t)h1 << 16),
                                  (uint32_t)h2 | ((uint32_t)h3 << 16));
            uint2 lp = make_uint2((uint32_t)l0 | ((uint32_t)l1 << 16),
                                  (uint32_t)l2 | ((uint32_t)l3 << 16));
            *(uint2*)(s0 + r * 80 + g * 8)          = hp;
            *(uint2*)(s0 + 10240 + r * 80 + g * 8)  = lp;
        }
#pragma unroll
        for (int i = 0; i < 2; i++) {
            int ch = tid + 256 * i;
            int r = ch >> 2, g = ch & 3;
            *(uint4*)(s0 + 20480 + r * 80 + g * 16) = rBh[i];
            *(uint4*)(s0 + 30720 + r * 80 + g * 16) = rBl[i];
        }
    };

    load_regs(0);
    for (int kt = 0; kt < 32; kt++) {
        store_smem(kt & 1);
        __syncthreads();
        if (kt + 1 < 32) load_regs(kt + 1);

        uint32_t sb = sb0 + (kt & 1) * 40960;
#pragma unroll
        for (int ks = 0; ks < 2; ks++) {
            int k0 = ks * 16;
            // A fragments via ldmatrix x4: lane -> row wm+mf*16+(l&15), k = k0+(l>>4)*8
            uint32_t ah[4][4], al[4][4];
            uint32_t arow = (uint32_t)(wm + (l & 15));
            uint32_t acol = (uint32_t)(k0 + (l >> 4) * 8);
#pragma unroll
            for (int mf = 0; mf < 4; mf++) {
                uint32_t off = ((arow + mf * 16) * GP + acol) * 2;
                ldsm4(ah[mf], sb + off);
                ldsm4(al[mf], sb + 10240 + off);
            }
            // B fragments: x4 covers two nf (n-pairs); lanes: n = wn+p*16+(l>>4)*8+(l&7), k = k0+((l>>3)&1)*8
            uint32_t bh2[4][2], bl2[4][2];
            uint32_t brow = (uint32_t)(wn + (l >> 4) * 8 + (l & 7));
            uint32_t bcol = (uint32_t)(k0 + ((l >> 3) & 1) * 8);
#pragma unroll
            for (int p = 0; p < 2; p++) {
                uint32_t off = ((brow + p * 16) * GP + bcol) * 2;
                uint32_t tb[4];
                ldsm4(tb, sb + 20480 + off);
                bh2[2*p][0] = tb[0]; bh2[2*p][1] = tb[1];
                bh2[2*p+1][0] = tb[2]; bh2[2*p+1][1] = tb[3];
                ldsm4(tb, sb + 30720 + off);
                bl2[2*p][0] = tb[0]; bl2[2*p][1] = tb[1];
                bl2[2*p+1][0] = tb[2]; bl2[2*p+1][1] = tb[3];
            }
#pragma unroll
            for (int nf = 0; nf < 4; nf++)
#pragma unroll
                for (int mf = 0; mf < 4; mf++) {
                    mma_bf16(acc[mf][nf], ah[mf], bh2[nf]);
                    mma_bf16(acc[mf][nf], al[mf], bh2[nf]);
                    mma_bf16(acc[mf][nf], ah[mf], bl2[nf]);
                }
        }
    }
}

// ---------------- GEMM1: qkv + RoPE epilogue ---------------------------------
__global__ __launch_bounds__(256) void qkv_mma_gemm(const float* __restrict__ x) {
    extern __shared__ char sm[];
    int bm = blockIdx.y * 128, bn = blockIdx.x * 128;
    float acc[4][4][4];
    gemm_core2(x, g_wqh, g_wql, bm, bn, sm, acc);

    int tid = threadIdx.x, l = tid & 31, w = tid >> 5;
    int wm = (w >> 2) * 64, wn = (w & 3) * 32;

#pragma unroll
    for (int mf = 0; mf < 4; mf++) {
#pragma unroll
        for (int half = 0; half < 2; half++) {
            int row = bm + wm + mf * 16 + (l >> 2) + half * 8;
            int b = row >> 11;
            int tok = row & (Nn - 1);
#pragma unroll
            for (int nf = 0; nf < 4; nf++) {
                int col = bn + wn + nf * 8 + (l & 3) * 2;   // even
                float y0 = acc[mf][nf][half * 2 + 0];
                float y1 = acc[mf][nf][half * 2 + 1];
                int region = col >> 10;
                int cc = col & 1023;
                int h = cc >> 6;
                int dd = cc & 63;
                size_t base = ((size_t)(b * Hh + h) * Nn + tok) * Dd;
                if (region == 2) {
                    *(float2*)(g_v + base + dd) = make_float2(y0, y1);
                } else {
                    float* dst = region ? g_k : g_q;
                    int i1 = dd >> 1;
                    float cs = g_cos[tok * 32 + i1];
                    float sn = g_sin[tok * 32 + i1];
                    dst[base + i1]      = y0 * cs - y1 * sn;
                    dst[base + i1 + 32] = y0 * sn + y1 * cs;
                }
            }
        }
    }
}

// ---------------- GEMM3: out = g_o @ WoutT + bias ----------------------------
__global__ __launch_bounds__(256) void out_mma_gemm(const float* __restrict__ bias,
                                                    float* __restrict__ out) {
    extern __shared__ char sm[];
    int bm = blockIdx.y * 128, bn = blockIdx.x * 128;
    float acc[4][4][4];
    gemm_core2(g_o, g_woh, g_wol, bm, bn, sm, acc);

    int tid = threadIdx.x, l = tid & 31, w = tid >> 5;
    int wm = (w >> 2) * 64, wn = (w & 3) * 32;

#pragma unroll
    for (int mf = 0; mf < 4; mf++) {
#pragma unroll
        for (int half = 0; half < 2; half++) {
            int row = bm + wm + mf * 16 + (l >> 2) + half * 8;
#pragma unroll
            for (int nf = 0; nf < 4; nf++) {
                int col = bn + wn + nf * 8 + (l & 3) * 2;
                float y0 = acc[mf][nf][half * 2 + 0] + bias[col];
                float y1 = acc[mf][nf][half * 2 + 1] + bias[col + 1];
                *(float2*)(out + (size_t)row * Cc + col) = make_float2(y0, y1);
            }
        }
    }
}

// ===================== Flash attention (R7 verbatim, proven) =================
#define AP 72
#define AT_SMEM 73728

__global__ __launch_bounds__(256) void flash_mma_kernel() {
    extern __shared__ char sm[];
    uint16_t* sQh = (uint16_t*)sm;
    uint16_t* sQl = (uint16_t*)(sm + 18432);
    uint16_t* sKh = (uint16_t*)(sm + 36864);
    uint16_t* sKl = (uint16_t*)(sm + 46080);
    uint16_t* sVh = (uint16_t*)(sm + 55296);
    uint16_t* sVl = (uint16_t*)(sm + 64512);

    int tid = threadIdx.x, l = tid & 31, w = tid >> 5;
    int wm = w * 16;
    int bh = blockIdx.y;
    int qb = blockIdx.x;
    int b = bh >> 4, h = bh & 15;

    const float* Qp = g_q + ((size_t)bh * Nn + qb * 128) * Dd;
#pragma unroll
    for (int i = 0; i < 8; i++) {
        int idx = tid + 256 * i;
        int r = idx >> 4, c4 = (idx & 15) * 4;
        float4 v = *(const float4*)(Qp + (size_t)r * Dd + c4);
        uint16_t h0,l0,h1,l1,h2,l2,h3,l3;
        fsplit(v.x, h0, l0); fsplit(v.y, h1, l1);
        fsplit(v.z, h2, l2); fsplit(v.w, h3, l3);
        uint32_t* ph = (uint32_t*)&sQh[r * AP + c4];
        uint32_t* pl = (uint32_t*)&sQl[r * AP + c4];
        ph[0] = (uint32_t)h0 | ((uint32_t)h1 << 16);
        ph[1] = (uint32_t)h2 | ((uint32_t)h3 << 16);
        pl[0] = (uint32_t)l0 | ((uint32_t)l1 << 16);
        pl[1] = (uint32_t)l2 | ((uint32_t)l3 << 16);
    }

    float O[8][4];
#pragma unroll
    for (int nf = 0; nf < 8; nf++)
#pragma unroll
        for (int i = 0; i < 4; i++) O[nf][i] = 0.0f;
    float mrow[2] = {-1e30f, -1e30f};
    float lsum[2] = {0.0f, 0.0f};

    const float* Kp = g_k + (size_t)bh * Nn * Dd;
    const float* Vp = g_v + (size_t)bh * Nn * Dd;

    const int ntiles = 2 * qb + 2;
    for (int t = 0; t < ntiles; t++) {
        float4 kv4[4], vv4[4];
#pragma unroll
        for (int i = 0; i < 4; i++) {
            int idx = tid + 256 * i;
            int r = idx >> 4, c4 = (idx & 15) * 4;
            kv4[i] = *(const float4*)(Kp + (size_t)(t * 64 + r) * Dd + c4);
            vv4[i] = *(const float4*)(Vp + (size_t)(t * 64 + r) * Dd + c4);
        }
        __syncthreads();
#pragma unroll
        for (int i = 0; i < 4; i++) {
            int idx = tid + 256 * i;
            int r = idx >> 4, c4 = (idx & 15) * 4;
            uint16_t h0,l0,h1,l1,h2,l2,h3,l3;
            fsplit(kv4[i].x, h0, l0); fsplit(kv4[i].y, h1, l1);
            fsplit(kv4[i].z, h2, l2); fsplit(kv4[i].w, h3, l3);
            uint32_t* ph = (uint32_t*)&sKh[r * AP + c4];
            uint32_t* pl = (uint32_t*)&sKl[r * AP + c4];
            ph[0] = (uint32_t)h0 | ((uint32_t)h1 << 16);
            ph[1] = (uint32_t)h2 | ((uint32_t)h3 << 16);
            pl[0] = (uint32_t)l0 | ((uint32_t)l1 << 16);
            pl[1] = (uint32_t)l2 | ((uint32_t)l3 << 16);
            float vs[4] = {vv4[i].x, vv4[i].y, vv4[i].z, vv4[i].w};
#pragma unroll
            for (int j = 0; j < 4; j++) {
                uint16_t hh, ll;
                fsplit(vs[j], hh, ll);
                sVh[(c4 + j) * AP + r] = hh;
                sVl[(c4 + j) * AP + r] = ll;
            }
        }
        __syncthreads();

        float S[8][4];
#pragma unroll
        for (int nf = 0; nf < 8; nf++)
#pragma unroll
            for (int i = 0; i < 4; i++) S[nf][i] = 0.0f;

#pragma unroll
        for (int ks = 0; ks < 4; ks++) {
            int kc = ks * 16 + (l & 3) * 2;
            int r = wm + (l >> 2);
            uint32_t qh[4], ql[4];
            qh[0] = *(const uint32_t*)&sQh[(r    ) * AP + kc];
            qh[1] = *(const uint32_t*)&sQh[(r + 8) * AP + kc];
            qh[2] = *(const uint32_t*)&sQh[(r    ) * AP + kc + 8];
            qh[3] = *(const uint32_t*)&sQh[(r + 8) * AP + kc + 8];
            ql[0] = *(const uint32_t*)&sQl[(r    ) * AP + kc];
            ql[1] = *(const uint32_t*)&sQl[(r + 8) * AP + kc];
            ql[2] = *(const uint32_t*)&sQl[(r    ) * AP + kc + 8];
            ql[3] = *(const uint32_t*)&sQl[(r + 8) * AP + kc + 8];
#pragma unroll
            for (int nf = 0; nf < 8; nf++) {
                int n = nf * 8 + (l >> 2);
                uint32_t kh2[2], kl2[2];
                kh2[0] = *(const uint32_t*)&sKh[n * AP + kc];
                kh2[1] = *(const uint32_t*)&sKh[n * AP + kc + 8];
                kl2[0] = *(const uint32_t*)&sKl[n * AP + kc];
                kl2[1] = *(const uint32_t*)&sKl[n * AP + kc + 8];
                mma_bf16(S[nf], qh, kh2);
                mma_bf16(S[nf], ql, kh2);
                mma_bf16(S[nf], qh, kl2);
            }
        }

        bool domask = (t >= 2 * qb);
#pragma unroll
        for (int nf = 0; nf < 8; nf++)
#pragma unroll
            for (int idx = 0; idx < 4; idx++) {
                float v = S[nf][idx] * SL2E;
                if (domask) {
                    int h2 = idx >> 1, ci = idx & 1;
                    int qg = qb * 128 + wm + (l >> 2) + h2 * 8;
                    int kg = t * 64 + nf * 8 + (l & 3) * 2 + ci;
                    if (kg > qg) v = -1e30f;
                }
                S[nf][idx] = v;
            }

#pragma unroll
        for (int h2 = 0; h2 < 2; h2++) {
            float mx = -1e30f;
#pragma unroll
            for (int nf = 0; nf < 8; nf++)
                mx = fmaxf(mx, fmaxf(S[nf][h2*2], S[nf][h2*2+1]));
            mx = fmaxf(mx, __shfl_xor_sync(0xffffffffu, mx, 1));
            mx = fmaxf(mx, __shfl_xor_sync(0xffffffffu, mx, 2));
            float mnew = fmaxf(mrow[h2], mx);
            float scl = ex2(mrow[h2] - mnew);
            float sum = 0.0f;
#pragma unroll
            for (int nf = 0; nf < 8; nf++) {
                float p0 = ex2(S[nf][h2*2]   - mnew);
                float p1 = ex2(S[nf][h2*2+1] - mnew);
                S[nf][h2*2]   = p0;
                S[nf][h2*2+1] = p1;
                sum += p0 + p1;
            }
            sum += __shfl_xor_sync(0xffffffffu, sum, 1);
            sum += __shfl_xor_sync(0xffffffffu, sum, 2);
            lsum[h2] = lsum[h2] * scl + sum;
            mrow[h2] = mnew;
#pragma unroll
            for (int nf = 0; nf < 8; nf++) {
                O[nf][h2*2]   *= scl;
                O[nf][h2*2+1] *= scl;
            }
        }

#pragma unroll
        for (int ks = 0; ks < 4; ks++) {
            uint32_t ph[4], pl[4];
#pragma unroll
            for (int half = 0; half < 2; half++) {
#pragma unroll
                for (int rr = 0; rr < 2; rr++) {
                    float v0 = S[2*ks + half][rr*2];
                    float v1 = S[2*ks + half][rr*2 + 1];
                    uint16_t a0, b0, a1, b1;
                    fsplit(v0, a0, b0);
                    fsplit(v1, a1, b1);
                    ph[half*2 + rr] = (uint32_t)a0 | ((uint32_t)a1 << 16);
                    pl[half*2 + rr] = (uint32_t)b0 | ((uint32_t)b1 << 16);
                }
            }
            int kc = ks * 16 + (l & 3) * 2;
#pragma unroll
            for (int nf = 0; nf < 8; nf++) {
                int n = nf * 8 + (l >> 2);
                uint32_t vh2[2], vl2[2];
                vh2[0] = *(const uint32_t*)&sVh[n * AP + kc];
                vh2[1] = *(const uint32_t*)&sVh[n * AP + kc + 8];
                vl2[0] = *(const uint32_t*)&sVl[n * AP + kc];
                vl2[1] = *(const uint32_t*)&sVl[n * AP + kc + 8];
                mma_bf16(O[nf], ph, vh2);
                mma_bf16(O[nf], pl, vh2);
                mma_bf16(O[nf], ph, vl2);
            }
        }
    }

    float inv[2] = {1.0f / lsum[0], 1.0f / lsum[1]};
#pragma unroll
    for (int nf = 0; nf < 8; nf++)
#pragma unroll
        for (int h2 = 0; h2 < 2; h2++) {
            int q = qb * 128 + wm + (l >> 2) + h2 * 8;
            int col = h * 64 + nf * 8 + (l & 3) * 2;
            size_t o = (size_t)(b * Nn + q) * Cc + col;
            *(float2*)(g_o + o) = make_float2(O[nf][h2*2] * inv[h2],
                                              O[nf][h2*2+1] * inv[h2]);
        }
}

// ---------------- launch -----------------------------------------------------
extern "C" void kernel_launch(void* const* d_in, const int* in_sizes, int n_in,
                              void* d_out, int out_size)
{
    (void)in_sizes; (void)n_in; (void)out_size;
    const float* x    = (const float*)d_in[0];
    const float* Wqkv = (const float*)d_in[1];
    const float* Wout = (const float*)d_in[2];
    const float* bout = (const float*)d_in[3];
    float* out = (float*)d_out;

    cudaFuncSetAttribute(qkv_mma_gemm, cudaFuncAttributeMaxDynamicSharedMemorySize, GEMM_SMEM);
    cudaFuncSetAttribute(out_mma_gemm, cudaFuncAttributeMaxDynamicSharedMemorySize, GEMM_SMEM);
    cudaFuncSetAttribute(flash_mma_kernel, cudaFuncAttributeMaxDynamicSharedMemorySize, AT_SMEM);

    rope_init_kernel<<<(Nn * 32 + 255) / 256, 256>>>();
    transpose_split_kernel<<<dim3(K3 / 32, Cc / 32), dim3(32, 8)>>>(Wqkv, Cc, K3, 0);
    transpose_split_kernel<<<dim3(Cc / 32, Cc / 32), dim3(32, 8)>>>(Wout, Cc, Cc, 1);
    qkv_mma_gemm<<<dim3(K3 / 128, Mtot / 128), 256, GEMM_SMEM>>>(x);
    flash_mma_kernel<<<dim3(Nn / 128, Bb * Hh), 256, AT_SMEM>>>();
    out_mma_gemm<<<dim3(Cc / 128, Mtot / 128), 256, GEMM_SMEM>>>(bout, out);
}